// round 3
// baseline (speedup 1.0000x reference)
#include <cuda_runtime.h>
#include <math.h>

// Problem dims
#define SEQ   256
#define BATCH 64
#define IDIM  1024
#define HDIM  1024
#define PLEN  256
#define PDIM  1024

// -------- device scratch (no runtime allocation allowed) --------
__device__ float g_gi[SEQ * BATCH * 3 * HDIM];      // 201 MB: precomputed input gates
__device__ float g_gh[BATCH * 3 * HDIM];            // per-step hidden gates
__device__ float g_h[BATCH * HDIM];                 // current hidden state
__device__ float g_query[SEQ * BATCH * PDIM];       // 67 MB
__device__ float g_scores[BATCH * SEQ * PLEN];      // 16 MB  [b][s][l]
__device__ float g_attn[BATCH * SEQ * PLEN];        // 16 MB  [b][s][l]

// =====================================================================
// Generic fp32 GEMM, C = A * W^T (+bias), both operands K-contiguous.
// All dims assumed multiples of tile sizes (true for every call site).
// =====================================================================
template<int BM, int BN, int BK, int TM, int TN>
__global__ void sgemm_nt(int M, int N, int K,
                         const float* __restrict__ A, int lda, long long bsA,
                         const float* __restrict__ W, int ldw, long long bsW,
                         float* __restrict__ C, int ldc, long long bsC,
                         const float* __restrict__ bias)
{
    constexpr int THREADS = (BM / TM) * (BN / TN);
    __shared__ float As[BK][BM + 4];
    __shared__ float Ws[BK][BN + 4];

    const int tid = threadIdx.x;
    const int n0 = blockIdx.x * BN;
    const int m0 = blockIdx.y * BM;
    A += (long long)blockIdx.z * bsA;
    W += (long long)blockIdx.z * bsW;
    C += (long long)blockIdx.z * bsC;

    const int tn0 = (tid % (BN / TN)) * TN;
    const int tm0 = (tid / (BN / TN)) * TM;

    float acc[TM][TN];
#pragma unroll
    for (int i = 0; i < TM; i++)
#pragma unroll
        for (int j = 0; j < TN; j++) acc[i][j] = 0.0f;

    constexpr int KV  = BK / 4;            // float4 chunks per k-row
    constexpr int RPP = THREADS / KV;      // rows loaded per pass
    const int lr = tid / KV;
    const int lc = (tid % KV) * 4;

    for (int k0 = 0; k0 < K; k0 += BK) {
#pragma unroll
        for (int r = 0; r < BM; r += RPP) {
            float4 v = *(const float4*)(A + (long long)(m0 + lr + r) * lda + k0 + lc);
            As[lc + 0][lr + r] = v.x; As[lc + 1][lr + r] = v.y;
            As[lc + 2][lr + r] = v.z; As[lc + 3][lr + r] = v.w;
        }
#pragma unroll
        for (int r = 0; r < BN; r += RPP) {
            float4 v = *(const float4*)(W + (long long)(n0 + lr + r) * ldw + k0 + lc);
            Ws[lc + 0][lr + r] = v.x; Ws[lc + 1][lr + r] = v.y;
            Ws[lc + 2][lr + r] = v.z; Ws[lc + 3][lr + r] = v.w;
        }
        __syncthreads();
#pragma unroll
        for (int kk = 0; kk < BK; kk++) {
            float a[TM], w[TN];
#pragma unroll
            for (int i = 0; i < TM; i++) a[i] = As[kk][tm0 + i];
#pragma unroll
            for (int j = 0; j < TN; j++) w[j] = Ws[kk][tn0 + j];
#pragma unroll
            for (int i = 0; i < TM; i++)
#pragma unroll
                for (int j = 0; j < TN; j++) acc[i][j] += a[i] * w[j];
        }
        __syncthreads();
    }

#pragma unroll
    for (int i = 0; i < TM; i++) {
#pragma unroll
        for (int j = 0; j < TN; j++) {
            float c = acc[i][j];
            if (bias) c += bias[n0 + tn0 + j];
            C[(long long)(m0 + tm0 + i) * ldc + n0 + tn0 + j] = c;
        }
    }
}

// =====================================================================
// Generic fp32 GEMM, C = A * B (A is MxK K-contig, B is KxN N-contig)
// =====================================================================
template<int BM, int BN, int BK, int TM, int TN>
__global__ void sgemm_nn(int M, int N, int K,
                         const float* __restrict__ A, int lda, long long bsA,
                         const float* __restrict__ B, int ldb, long long bsB,
                         float* __restrict__ C, int ldc, long long bsC)
{
    constexpr int THREADS = (BM / TM) * (BN / TN);
    __shared__ float As[BK][BM + 4];
    __shared__ float Bs[BK][BN + 4];

    const int tid = threadIdx.x;
    const int n0 = blockIdx.x * BN;
    const int m0 = blockIdx.y * BM;
    A += (long long)blockIdx.z * bsA;
    B += (long long)blockIdx.z * bsB;
    C += (long long)blockIdx.z * bsC;

    const int tn0 = (tid % (BN / TN)) * TN;
    const int tm0 = (tid / (BN / TN)) * TM;

    float acc[TM][TN];
#pragma unroll
    for (int i = 0; i < TM; i++)
#pragma unroll
        for (int j = 0; j < TN; j++) acc[i][j] = 0.0f;

    // A loader (transpose into smem)
    constexpr int KVA  = BK / 4;
    constexpr int RPPA = THREADS / KVA;
    const int alr = tid / KVA;
    const int alc = (tid % KVA) * 4;
    // B loader (direct)
    constexpr int KVB  = BN / 4;
    constexpr int RPPB = THREADS / KVB;
    const int blr = tid / KVB;
    const int blc = (tid % KVB) * 4;

    for (int k0 = 0; k0 < K; k0 += BK) {
#pragma unroll
        for (int r = 0; r < BM; r += RPPA) {
            float4 v = *(const float4*)(A + (long long)(m0 + alr + r) * lda + k0 + alc);
            As[alc + 0][alr + r] = v.x; As[alc + 1][alr + r] = v.y;
            As[alc + 2][alr + r] = v.z; As[alc + 3][alr + r] = v.w;
        }
#pragma unroll
        for (int r = 0; r < BK; r += RPPB) {
            float4 v = *(const float4*)(B + (long long)(k0 + blr + r) * ldb + n0 + blc);
            *(float4*)&Bs[blr + r][blc] = v;
        }
        __syncthreads();
#pragma unroll
        for (int kk = 0; kk < BK; kk++) {
            float a[TM], w[TN];
#pragma unroll
            for (int i = 0; i < TM; i++) a[i] = As[kk][tm0 + i];
#pragma unroll
            for (int j = 0; j < TN; j++) w[j] = Bs[kk][tn0 + j];
#pragma unroll
            for (int i = 0; i < TM; i++)
#pragma unroll
                for (int j = 0; j < TN; j++) acc[i][j] += a[i] * w[j];
        }
        __syncthreads();
    }

#pragma unroll
    for (int i = 0; i < TM; i++)
#pragma unroll
        for (int j = 0; j < TN; j++)
            C[(long long)(m0 + tm0 + i) * ldc + n0 + tn0 + j] = acc[i][j];
}

// =====================================================================
// Pointwise kernels
// =====================================================================
__global__ void init_h_kernel(float* __restrict__ h, const float* __restrict__ h_init)
{
    int idx = blockIdx.x * blockDim.x + threadIdx.x;   // 65536 threads
    h[idx] = h_init[idx & (HDIM - 1)];
}

__global__ void gru_gates_kernel(int s,
                                 const float* __restrict__ gi_step,   // [B, 3H] (has b_ih)
                                 const float* __restrict__ gh,        // [B, 3H] (has b_hh)
                                 float* __restrict__ h,               // [B, H] in/out
                                 const int* __restrict__ length,
                                 float* __restrict__ out_hs,          // [S, B, 2H]
                                 float* __restrict__ out_hlast)       // [B, H]
{
    int idx = blockIdx.x * blockDim.x + threadIdx.x;   // 0..65535
    int b = idx >> 10;
    int j = idx & (HDIM - 1);

    float ir = gi_step[b * 3 * HDIM + j];
    float iz = gi_step[b * 3 * HDIM + HDIM + j];
    float in_ = gi_step[b * 3 * HDIM + 2 * HDIM + j];
    float hr = gh[b * 3 * HDIM + j];
    float hz = gh[b * 3 * HDIM + HDIM + j];
    float hn = gh[b * 3 * HDIM + 2 * HDIM + j];

    float r = 1.0f / (1.0f + expf(-(ir + hr)));
    float z = 1.0f / (1.0f + expf(-(iz + hz)));
    float n = tanhf(in_ + r * hn);
    float hv = h[idx];
    float keep = (s < length[b]) ? 1.0f : 0.0f;
    float hnew = (n + z * (hv - n)) * keep;

    h[idx] = hnew;
    out_hs[(long long)s * (BATCH * 2 * HDIM) + b * (2 * HDIM) + j] = hnew;
    if (s == SEQ - 1) out_hlast[idx] = hnew;
}

__global__ void attn_softmax_kernel(const float* __restrict__ scores,   // [b][s][l]
                                    const int* __restrict__ post_length,
                                    float* __restrict__ attn_scratch,   // [b][s][l]
                                    float* __restrict__ out_attn)       // [s][l][b]
{
    int s = blockIdx.x;
    int b = blockIdx.y;
    int l = threadIdx.x;   // PLEN = 256 threads

    float sc = scores[((long long)b * SEQ + s) * PLEN + l];
    if (l >= post_length[b]) sc = -1000000000.0f;

    __shared__ float red[PLEN];
    red[l] = sc;
    __syncthreads();
#pragma unroll
    for (int o = PLEN / 2; o > 0; o >>= 1) {
        if (l < o) red[l] = fmaxf(red[l], red[l + o]);
        __syncthreads();
    }
    float mx = red[0];
    __syncthreads();

    float e = expf(sc - mx);
    red[l] = e;
    __syncthreads();
#pragma unroll
    for (int o = PLEN / 2; o > 0; o >>= 1) {
        if (l < o) red[l] += red[l + o];
        __syncthreads();
    }
    float a = e / red[0];

    attn_scratch[((long long)b * SEQ + s) * PLEN + l] = a;
    out_attn[(long long)s * (PLEN * BATCH) + l * BATCH + b] = a;
}

// =====================================================================
// launch
// =====================================================================
extern "C" void kernel_launch(void* const* d_in, const int* in_sizes, int n_in,
                              void* d_out, int out_size)
{
    (void)in_sizes; (void)n_in; (void)out_size;

    const float* incoming = (const float*)d_in[0];   // [S, B, I]
    const float* post     = (const float*)d_in[1];   // [PL, B, P]
    const float* h_init   = (const float*)d_in[2];   // [1,1,H]
    const float* W_ih     = (const float*)d_in[3];   // [3H, I]
    const float* W_hh     = (const float*)d_in[4];   // [3H, H]
    const float* b_ih     = (const float*)d_in[5];
    const float* b_hh     = (const float*)d_in[6];
    const float* Wq       = (const float*)d_in[7];   // [P, H]
    const float* bq       = (const float*)d_in[8];
    const int*   length      = (const int*)d_in[9];
    const int*   post_length = (const int*)d_in[10];

    float* out       = (float*)d_out;
    float* out_hlast = out;                                   // [B, H]
    float* out_hs    = out + BATCH * HDIM;                    // [S, B, 2H]
    float* out_attn  = out_hs + (long long)SEQ * BATCH * 2 * HDIM;  // [S, PL, B]

    float *gi, *gh, *h, *query, *scores, *attn;
    cudaGetSymbolAddress((void**)&gi,     g_gi);
    cudaGetSymbolAddress((void**)&gh,     g_gh);
    cudaGetSymbolAddress((void**)&h,      g_h);
    cudaGetSymbolAddress((void**)&query,  g_query);
    cudaGetSymbolAddress((void**)&scores, g_scores);
    cudaGetSymbolAddress((void**)&attn,   g_attn);

    const int MALL = SEQ * BATCH;   // 16384

    // Phase A: gi = incoming @ W_ih^T + b_ih for all steps  [16384, 3072]
    sgemm_nt<128, 128, 16, 8, 8>
        <<<dim3(3 * HDIM / 128, MALL / 128), 256>>>(
            MALL, 3 * HDIM, IDIM,
            incoming, IDIM, 0,
            W_ih, IDIM, 0,
            gi, 3 * HDIM, 0,
            b_ih);

    // init hidden state
    init_h_kernel<<<64, 1024>>>(h, h_init);

    // Phase B: sequential GRU recurrence
    for (int s = 0; s < SEQ; s++) {
        sgemm_nt<64, 32, 32, 4, 2>
            <<<dim3(3 * HDIM / 32, 1), 256>>>(
                BATCH, 3 * HDIM, HDIM,
                h, HDIM, 0,
                W_hh, HDIM, 0,
                gh, 3 * HDIM, 0,
                b_hh);
        gru_gates_kernel<<<256, 256>>>(
            s, gi + (long long)s * BATCH * 3 * HDIM, gh, h,
            length, out_hs, out_hlast);
    }

    // Phase C: query = h_all @ Wq^T + bq, reading h from hs region (row stride 2H)
    sgemm_nt<128, 128, 16, 8, 8>
        <<<dim3(PDIM / 128, MALL / 128), 256>>>(
            MALL, PDIM, HDIM,
            out_hs, 2 * HDIM, 0,
            Wq, HDIM, 0,
            query, PDIM, 0,
            bq);

    // Phase D1: scores_b[s][l] = Q_b[s] . post_b[l]   (batched over b via grid.z)
    sgemm_nt<128, 128, 16, 8, 8>
        <<<dim3(PLEN / 128, SEQ / 128, BATCH), 256>>>(
            SEQ, PLEN, PDIM,
            query, BATCH * PDIM, PDIM,        // A = g_query + b*P, lda = B*P
            post, BATCH * PDIM, PDIM,         // W = post + b*P,    ldw = B*P
            scores, PLEN, (long long)SEQ * PLEN,
            (const float*)nullptr);

    // Phase D2: masked softmax over l
    attn_softmax_kernel<<<dim3(SEQ, BATCH), PLEN>>>(scores, post_length, attn, out_attn);

    // Phase D3: context_b = attn_b [S,L] @ post_b [L,P] -> hs[:, b, H:2H]
    sgemm_nn<128, 128, 16, 8, 8>
        <<<dim3(PDIM / 128, SEQ / 128, BATCH), 256>>>(
            SEQ, PDIM, PLEN,
            attn, PLEN, (long long)SEQ * PLEN,
            post, BATCH * PDIM, PDIM,
            out_hs + HDIM, BATCH * 2 * HDIM, 2 * HDIM);
}

// round 6
// speedup vs baseline: 1.4769x; 1.4769x over previous
#include <cuda_runtime.h>
#include <math.h>

// Problem dims
#define SEQ   256
#define BATCH 64
#define IDIM  1024
#define HDIM  1024
#define PLEN  256
#define PDIM  1024

#define RBLOCKS  256
#define RTHREADS 256

// -------- device scratch (no runtime allocation allowed) --------
__device__ float g_gi[SEQ * BATCH * 3 * HDIM];      // precomputed input gates
__device__ float g_h2[2 * BATCH * HDIM];            // double-buffered hidden state
__device__ float g_query[SEQ * BATCH * PDIM];
__device__ float g_scores[BATCH * SEQ * PLEN];
__device__ float g_attn[BATCH * SEQ * PLEN];
__device__ unsigned g_bar;                          // grid barrier counter (memset each launch)

// =====================================================================
// Generic fp32 GEMM, C = A * W^T (+bias)
// =====================================================================
template<int BM, int BN, int BK, int TM, int TN>
__global__ void sgemm_nt(int M, int N, int K,
                         const float* __restrict__ A, int lda, long long bsA,
                         const float* __restrict__ W, int ldw, long long bsW,
                         float* __restrict__ C, int ldc, long long bsC,
                         const float* __restrict__ bias)
{
    constexpr int THREADS = (BM / TM) * (BN / TN);
    __shared__ float As[BK][BM + 4];
    __shared__ float Ws[BK][BN + 4];

    const int tid = threadIdx.x;
    const int n0 = blockIdx.x * BN;
    const int m0 = blockIdx.y * BM;
    A += (long long)blockIdx.z * bsA;
    W += (long long)blockIdx.z * bsW;
    C += (long long)blockIdx.z * bsC;

    const int tn0 = (tid % (BN / TN)) * TN;
    const int tm0 = (tid / (BN / TN)) * TM;

    float acc[TM][TN];
#pragma unroll
    for (int i = 0; i < TM; i++)
#pragma unroll
        for (int j = 0; j < TN; j++) acc[i][j] = 0.0f;

    constexpr int KV  = BK / 4;
    constexpr int RPP = THREADS / KV;
    const int lr = tid / KV;
    const int lc = (tid % KV) * 4;

    for (int k0 = 0; k0 < K; k0 += BK) {
#pragma unroll
        for (int r = 0; r < BM; r += RPP) {
            float4 v = *(const float4*)(A + (long long)(m0 + lr + r) * lda + k0 + lc);
            As[lc + 0][lr + r] = v.x; As[lc + 1][lr + r] = v.y;
            As[lc + 2][lr + r] = v.z; As[lc + 3][lr + r] = v.w;
        }
#pragma unroll
        for (int r = 0; r < BN; r += RPP) {
            float4 v = *(const float4*)(W + (long long)(n0 + lr + r) * ldw + k0 + lc);
            Ws[lc + 0][lr + r] = v.x; Ws[lc + 1][lr + r] = v.y;
            Ws[lc + 2][lr + r] = v.z; Ws[lc + 3][lr + r] = v.w;
        }
        __syncthreads();
#pragma unroll
        for (int kk = 0; kk < BK; kk++) {
            float a[TM], w[TN];
#pragma unroll
            for (int i = 0; i < TM; i++) a[i] = As[kk][tm0 + i];
#pragma unroll
            for (int j = 0; j < TN; j++) w[j] = Ws[kk][tn0 + j];
#pragma unroll
            for (int i = 0; i < TM; i++)
#pragma unroll
                for (int j = 0; j < TN; j++) acc[i][j] += a[i] * w[j];
        }
        __syncthreads();
    }

#pragma unroll
    for (int i = 0; i < TM; i++) {
#pragma unroll
        for (int j = 0; j < TN; j++) {
            float c = acc[i][j];
            if (bias) c += bias[n0 + tn0 + j];
            C[(long long)(m0 + tm0 + i) * ldc + n0 + tn0 + j] = c;
        }
    }
}

// =====================================================================
// Generic fp32 GEMM, C = A * B
// =====================================================================
template<int BM, int BN, int BK, int TM, int TN>
__global__ void sgemm_nn(int M, int N, int K,
                         const float* __restrict__ A, int lda, long long bsA,
                         const float* __restrict__ B, int ldb, long long bsB,
                         float* __restrict__ C, int ldc, long long bsC)
{
    constexpr int THREADS = (BM / TM) * (BN / TN);
    __shared__ float As[BK][BM + 4];
    __shared__ float Bs[BK][BN + 4];

    const int tid = threadIdx.x;
    const int n0 = blockIdx.x * BN;
    const int m0 = blockIdx.y * BM;
    A += (long long)blockIdx.z * bsA;
    B += (long long)blockIdx.z * bsB;
    C += (long long)blockIdx.z * bsC;

    const int tn0 = (tid % (BN / TN)) * TN;
    const int tm0 = (tid / (BN / TN)) * TM;

    float acc[TM][TN];
#pragma unroll
    for (int i = 0; i < TM; i++)
#pragma unroll
        for (int j = 0; j < TN; j++) acc[i][j] = 0.0f;

    constexpr int KVA  = BK / 4;
    constexpr int RPPA = THREADS / KVA;
    const int alr = tid / KVA;
    const int alc = (tid % KVA) * 4;
    constexpr int KVB  = BN / 4;
    constexpr int RPPB = THREADS / KVB;
    const int blr = tid / KVB;
    const int blc = (tid % KVB) * 4;

    for (int k0 = 0; k0 < K; k0 += BK) {
#pragma unroll
        for (int r = 0; r < BM; r += RPPA) {
            float4 v = *(const float4*)(A + (long long)(m0 + alr + r) * lda + k0 + alc);
            As[alc + 0][alr + r] = v.x; As[alc + 1][alr + r] = v.y;
            As[alc + 2][alr + r] = v.z; As[alc + 3][alr + r] = v.w;
        }
#pragma unroll
        for (int r = 0; r < BK; r += RPPB) {
            float4 v = *(const float4*)(B + (long long)(k0 + blr + r) * ldb + n0 + blc);
            *(float4*)&Bs[blr + r][blc] = v;
        }
        __syncthreads();
#pragma unroll
        for (int kk = 0; kk < BK; kk++) {
            float a[TM], w[TN];
#pragma unroll
            for (int i = 0; i < TM; i++) a[i] = As[kk][tm0 + i];
#pragma unroll
            for (int j = 0; j < TN; j++) w[j] = Bs[kk][tn0 + j];
#pragma unroll
            for (int i = 0; i < TM; i++)
#pragma unroll
                for (int j = 0; j < TN; j++) acc[i][j] += a[i] * w[j];
        }
        __syncthreads();
    }

#pragma unroll
    for (int i = 0; i < TM; i++)
#pragma unroll
        for (int j = 0; j < TN; j++)
            C[(long long)(m0 + tm0 + i) * ldc + n0 + tn0 + j] = acc[i][j];
}

// =====================================================================
// Persistent GRU recurrence
//   256 blocks x 256 threads, all co-resident (2 blocks/SM).
//   Block owns 4 hidden columns j (-> 12 W_hh rows), W slice stationary in
//   smem for all 256 steps. h broadcast per step via cp.async.cg (L2-only,
//   avoids stale L1 across the manual grid barrier) in 16 double-buffered
//   4096-float chunks. Thread (bg, ks): bg = tid/16 owns batches
//   [4bg,4bg+4), ks = tid%16 owns a k-slice; partials reduced by 16-lane
//   shuffle butterfly, then each lane computes one (b, j) gate update.
// =====================================================================
__device__ __forceinline__ void cp_async16(void* smem_dst, const void* gmem_src)
{
    unsigned ds = (unsigned)__cvta_generic_to_shared(smem_dst);
    asm volatile("cp.async.cg.shared.global [%0], [%1], 16;\n" :: "r"(ds), "l"(gmem_src));
}

extern __shared__ float rsm[];   // [12*1024] W slice | 2 x [64*64] h chunk buffers

__global__ void __launch_bounds__(RTHREADS, 2)
gru_persistent(const float* __restrict__ gi,
               const float* __restrict__ W_hh,
               const float* __restrict__ b_hh,
               const float* __restrict__ h_init,
               const int* __restrict__ length,
               float* __restrict__ h2,          // [2][B*H]
               float* __restrict__ out_hs,      // [S][B][2H]
               float* __restrict__ out_hlast,   // [B][H]
               unsigned* __restrict__ bar)
{
    const int tid = threadIdx.x;
    const int bg  = tid >> 4;        // 0..15 -> batches [4bg, 4bg+4)
    const int ks  = tid & 15;        // k-slice id / gate-lane id
    const int j0  = blockIdx.x * 4;
    const int b   = bg * 4 + (ks >> 2);
    const int j   = j0 + (ks & 3);

    float* Ws  = rsm;                // 12 x 1024 floats
    float* hb0 = rsm + 12 * 1024;    // 64 x 64 floats (one chunk)
    float* hb1 = hb0 + 64 * 64;

    // ---- load stationary W_hh slice (cc = jj*3 + g -> row g*1024 + j0 + jj)
    for (int v = tid; v < 12 * 256; v += RTHREADS) {
        int cc = v >> 8;
        int cq = v & 255;
        int row = (cc % 3) * 1024 + j0 + (cc / 3);
        ((float4*)Ws)[cc * 256 + cq] = ((const float4*)W_hh)[row * 256 + cq];
    }

    const float bh_r = b_hh[j];
    const float bh_z = b_hh[1024 + j];
    const float bh_n = b_hh[2048 + j];
    const int   len_b = length[b];

    // ---- init h buffer 0 (grid covers exactly 64*1024 elements)
    {
        int v = blockIdx.x * RTHREADS + tid;
        h2[v] = h_init[v & (HDIM - 1)];
    }

    // ---- barrier: h init visible everywhere
    unsigned phase = 1;
    {
        __threadfence(); __syncthreads();
        if (tid == 0) {
            atomicAdd(bar, 1u);
            while (*((volatile unsigned*)bar) < phase * RBLOCKS) { __nanosleep(32); }
        }
        __syncthreads();
    }

    for (int s = 0; s < SEQ; s++) {
        const float* hcur = h2 + (s & 1) * (BATCH * HDIM);
        float*       hnxt = h2 + ((s + 1) & 1) * (BATCH * HDIM);
        const float4* hc4 = (const float4*)hcur;   // rows of 256 float4

        // prefetch gi + h_old early (consumed after the k-loop)
        const float* gis = gi + (long long)s * (BATCH * 3 * HDIM) + b * 3 * HDIM;
        float gi_r  = __ldg(&gis[j]);
        float gi_z  = __ldg(&gis[1024 + j]);
        float gi_n  = __ldg(&gis[2048 + j]);
        float h_old = __ldcg(&hcur[b * 1024 + j]);

        float acc[4][12];
#pragma unroll
        for (int i = 0; i < 4; i++)
#pragma unroll
            for (int cc = 0; cc < 12; cc++) acc[i][cc] = 0.0f;

        // stage chunk 0: 1024 float4s, 256 threads x 4 iterations
        {
            float4* dst = (float4*)hb0;
#pragma unroll
            for (int i = 0; i < 4; i++) {
                int idx = i * 256 + tid;            // 0..1023
                int bb = idx >> 4, kq = idx & 15;   // bb: batch 0..63, kq: float4 0..15
                cp_async16(&dst[bb * 16 + kq], &hc4[bb * 256 + kq]);
            }
            asm volatile("cp.async.commit_group;\n");
        }

        for (int c = 0; c < 16; c++) {
            const float* cur = (c & 1) ? hb1 : hb0;
            float*       nxt = (c & 1) ? hb0 : hb1;
            if (c + 1 < 16) {
                float4* dst = (float4*)nxt;
#pragma unroll
                for (int i = 0; i < 4; i++) {
                    int idx = i * 256 + tid;
                    int bb = idx >> 4, kq = idx & 15;
                    cp_async16(&dst[bb * 16 + kq], &hc4[bb * 256 + (c + 1) * 16 + kq]);
                }
                asm volatile("cp.async.commit_group;\n");
                asm volatile("cp.async.wait_group 1;\n");
            } else {
                asm volatile("cp.async.wait_group 0;\n");
            }
            __syncthreads();

            // compute: 4 batches x 12 cols x 4 k's
            float4 ha[4];
#pragma unroll
            for (int i = 0; i < 4; i++)
                ha[i] = *(const float4*)&cur[(bg * 4 + i) * 64 + ks * 4];
#pragma unroll
            for (int cc = 0; cc < 12; cc++) {
                float4 wv = *(const float4*)&Ws[cc * 1024 + c * 64 + ks * 4];
#pragma unroll
                for (int i = 0; i < 4; i++) {
                    acc[i][cc] += ha[i].x * wv.x;
                    acc[i][cc] += ha[i].y * wv.y;
                    acc[i][cc] += ha[i].z * wv.z;
                    acc[i][cc] += ha[i].w * wv.w;
                }
            }
            __syncthreads();
        }

        // butterfly reduce over 16 k-slices (stays within each 16-lane half)
#pragma unroll
        for (int off = 8; off > 0; off >>= 1)
#pragma unroll
            for (int i = 0; i < 4; i++)
#pragma unroll
                for (int cc = 0; cc < 12; cc++)
                    acc[i][cc] += __shfl_xor_sync(0xffffffffu, acc[i][cc], off);

        // fused gates: lane handles (b, j)
        {
            int bi = ks >> 2, jj = ks & 3;
            float ghr = acc[bi][jj * 3 + 0] + bh_r;
            float ghz = acc[bi][jj * 3 + 1] + bh_z;
            float ghn = acc[bi][jj * 3 + 2] + bh_n;
            float r = 1.0f / (1.0f + expf(-(gi_r + ghr)));
            float z = 1.0f / (1.0f + expf(-(gi_z + ghz)));
            float n = tanhf(gi_n + r * ghn);
            float keep = (s < len_b) ? 1.0f : 0.0f;
            float hnew = (n + z * (h_old - n)) * keep;

            hnxt[b * 1024 + j] = hnew;
            out_hs[(long long)s * (BATCH * 2 * HDIM) + b * (2 * HDIM) + j] = hnew;
            if (s == SEQ - 1) out_hlast[b * 1024 + j] = hnew;
        }

        // end-of-step barrier
        phase++;
        __threadfence(); __syncthreads();
        if (tid == 0) {
            atomicAdd(bar, 1u);
            while (*((volatile unsigned*)bar) < phase * RBLOCKS) { __nanosleep(32); }
        }
        __syncthreads();
    }
}

// =====================================================================
// Softmax
// =====================================================================
__global__ void attn_softmax_kernel(const float* __restrict__ scores,   // [b][s][l]
                                    const int* __restrict__ post_length,
                                    float* __restrict__ attn_scratch,   // [b][s][l]
                                    float* __restrict__ out_attn)       // [s][l][b]
{
    int s = blockIdx.x;
    int b = blockIdx.y;
    int l = threadIdx.x;

    float sc = scores[((long long)b * SEQ + s) * PLEN + l];
    if (l >= post_length[b]) sc = -1000000000.0f;

    __shared__ float red[PLEN];
    red[l] = sc;
    __syncthreads();
#pragma unroll
    for (int o = PLEN / 2; o > 0; o >>= 1) {
        if (l < o) red[l] = fmaxf(red[l], red[l + o]);
        __syncthreads();
    }
    float mx = red[0];
    __syncthreads();

    float e = expf(sc - mx);
    red[l] = e;
    __syncthreads();
#pragma unroll
    for (int o = PLEN / 2; o > 0; o >>= 1) {
        if (l < o) red[l] += red[l + o];
        __syncthreads();
    }
    float a = e / red[0];

    attn_scratch[((long long)b * SEQ + s) * PLEN + l] = a;
    out_attn[(long long)s * (PLEN * BATCH) + l * BATCH + b] = a;
}

// =====================================================================
// launch
// =====================================================================
extern "C" void kernel_launch(void* const* d_in, const int* in_sizes, int n_in,
                              void* d_out, int out_size)
{
    (void)in_sizes; (void)n_in; (void)out_size;

    const float* incoming = (const float*)d_in[0];
    const float* post     = (const float*)d_in[1];
    const float* h_init   = (const float*)d_in[2];
    const float* W_ih     = (const float*)d_in[3];
    const float* W_hh     = (const float*)d_in[4];
    const float* b_ih     = (const float*)d_in[5];
    const float* b_hh     = (const float*)d_in[6];
    const float* Wq       = (const float*)d_in[7];
    const float* bq       = (const float*)d_in[8];
    const int*   length      = (const int*)d_in[9];
    const int*   post_length = (const int*)d_in[10];

    float* out       = (float*)d_out;
    float* out_hlast = out;                                   // [B, H]
    float* out_hs    = out + BATCH * HDIM;                    // [S, B, 2H]
    float* out_attn  = out_hs + (long long)SEQ * BATCH * 2 * HDIM;  // [S, PL, B]

    float *gi, *h2, *query, *scores, *attn;
    unsigned* bar;
    cudaGetSymbolAddress((void**)&gi,     g_gi);
    cudaGetSymbolAddress((void**)&h2,     g_h2);
    cudaGetSymbolAddress((void**)&query,  g_query);
    cudaGetSymbolAddress((void**)&scores, g_scores);
    cudaGetSymbolAddress((void**)&attn,   g_attn);
    cudaGetSymbolAddress((void**)&bar,    g_bar);

    cudaFuncSetAttribute(gru_persistent,
                         cudaFuncAttributeMaxDynamicSharedMemorySize, 81920);

    const int MALL = SEQ * BATCH;   // 16384

    // Phase A: gi = incoming @ W_ih^T + b_ih for all steps  [16384, 3072]
    sgemm_nt<128, 128, 16, 8, 8>
        <<<dim3(3 * HDIM / 128, MALL / 128), 256>>>(
            MALL, 3 * HDIM, IDIM,
            incoming, IDIM, 0,
            W_ih, IDIM, 0,
            gi, 3 * HDIM, 0,
            b_ih);

    // Phase B: persistent fused GRU recurrence
    cudaMemsetAsync(bar, 0, sizeof(unsigned));
    gru_persistent<<<RBLOCKS, RTHREADS, 81920>>>(
        gi, W_hh, b_hh, h_init, length, h2, out_hs, out_hlast, bar);

    // Phase C: query = h_all @ Wq^T + bq (h read from hs region, stride 2H)
    sgemm_nt<128, 128, 16, 8, 8>
        <<<dim3(PDIM / 128, MALL / 128), 256>>>(
            MALL, PDIM, HDIM,
            out_hs, 2 * HDIM, 0,
            Wq, HDIM, 0,
            query, PDIM, 0,
            bq);

    // Phase D1: scores_b = Q_b @ post_b^T (batched over b)
    sgemm_nt<128, 128, 16, 8, 8>
        <<<dim3(PLEN / 128, SEQ / 128, BATCH), 256>>>(
            SEQ, PLEN, PDIM,
            query, BATCH * PDIM, PDIM,
            post, BATCH * PDIM, PDIM,
            scores, PLEN, (long long)SEQ * PLEN,
            (const float*)nullptr);

    // Phase D2: masked softmax over l
    attn_softmax_kernel<<<dim3(SEQ, BATCH), PLEN>>>(scores, post_length, attn, out_attn);

    // Phase D3: context_b = attn_b @ post_b
    sgemm_nn<128, 128, 16, 8, 8>
        <<<dim3(PDIM / 128, SEQ / 128, BATCH), 256>>>(
            SEQ, PDIM, PLEN,
            attn, PLEN, (long long)SEQ * PLEN,
            post, BATCH * PDIM, PDIM,
            out_hs + HDIM, BATCH * 2 * HDIM, 2 * HDIM);
}

// round 8
// speedup vs baseline: 1.6397x; 1.1102x over previous
#include <cuda_runtime.h>
#include <math.h>

// Problem dims
#define SEQ   256
#define BATCH 64
#define IDIM  1024
#define HDIM  1024
#define PLEN  256
#define PDIM  1024

#define RBLOCKS  256
#define RTHREADS 256

// -------- device scratch (no runtime allocation allowed) --------
__device__ float g_gi[SEQ * BATCH * 3 * HDIM];      // precomputed input gates
__device__ float g_h2[2 * BATCH * HDIM];            // double-buffered hidden state
__device__ float g_query[SEQ * BATCH * PDIM];
__device__ float g_scores[BATCH * SEQ * PLEN];
__device__ float g_attn[BATCH * SEQ * PLEN];
__device__ unsigned g_bar;                          // grid barrier counter

// =====================================================================
// helpers
// =====================================================================
__device__ __forceinline__ void cp_async16(void* smem_dst, const void* gmem_src)
{
    unsigned ds = (unsigned)__cvta_generic_to_shared(smem_dst);
    asm volatile("cp.async.cg.shared.global [%0], [%1], 16;\n" :: "r"(ds), "l"(gmem_src));
}

__device__ __forceinline__ unsigned f2tf(float x)
{
    unsigned r; asm("cvt.rna.tf32.f32 %0, %1;" : "=r"(r) : "f"(x)); return r;
}

__device__ __forceinline__ void mma8(float* c,
                                     unsigned a0, unsigned a1, unsigned a2, unsigned a3,
                                     unsigned b0, unsigned b1)
{
    asm volatile("mma.sync.aligned.m16n8k8.row.col.f32.tf32.tf32.f32 "
                 "{%0,%1,%2,%3},{%4,%5,%6,%7},{%8,%9},{%0,%1,%2,%3};"
                 : "+f"(c[0]), "+f"(c[1]), "+f"(c[2]), "+f"(c[3])
                 : "r"(a0), "r"(a1), "r"(a2), "r"(a3), "r"(b0), "r"(b1));
}

// =====================================================================
// Tensor-core tf32 (3xTF32) GEMM, C = A * W^T (+bias)
//   A [M,K] rows stride lda;  W [N,K] rows stride ldw.  128x128x16 tiles,
//   8 warps (4M x 2N), warp tile 32x64, 2-stage cp.async pipeline.
//   smem layout [row][k] stride 20 -> conflict-free fragment loads.
// =====================================================================
__global__ void __launch_bounds__(256)
tgemm_nt(int M, int N, int K,
         const float* __restrict__ A, long long lda, long long bsA,
         const float* __restrict__ W, long long ldw, long long bsW,
         float* __restrict__ C, long long ldc, long long bsC,
         const float* __restrict__ bias)
{
    __shared__ float sA[2][128 * 20];
    __shared__ float sB[2][128 * 20];

    const int tid = threadIdx.x;
    const int n0 = blockIdx.x * 128;
    const int m0 = blockIdx.y * 128;
    A += (long long)blockIdx.z * bsA;
    W += (long long)blockIdx.z * bsW;
    C += (long long)blockIdx.z * bsC;

    const int w    = tid >> 5;
    const int lane = tid & 31;
    const int lq   = lane >> 2;       // groupID
    const int lr   = lane & 3;        // threadID_in_group
    const int wm   = (w & 3) * 32;
    const int wn   = (w >> 2) * 64;

    float acc[2][8][4];
#pragma unroll
    for (int mt = 0; mt < 2; mt++)
#pragma unroll
        for (int nt = 0; nt < 8; nt++)
#pragma unroll
            for (int i = 0; i < 4; i++) acc[mt][nt][i] = 0.0f;

    const int nkt = K >> 4;

    auto load_stage = [&](int s, int kt) {
#pragma unroll
        for (int i = 0; i < 2; i++) {
            int idx = i * 256 + tid;          // 0..511
            int row = idx >> 2, c4 = idx & 3; // row 0..127, float4 slot 0..3
            cp_async16(&sA[s][row * 20 + c4 * 4],
                       A + (long long)(m0 + row) * lda + kt * 16 + c4 * 4);
            cp_async16(&sB[s][row * 20 + c4 * 4],
                       W + (long long)(n0 + row) * ldw + kt * 16 + c4 * 4);
        }
        asm volatile("cp.async.commit_group;\n");
    };

    load_stage(0, 0);

    for (int kt = 0; kt < nkt; kt++) {
        int cur = kt & 1;
        if (kt + 1 < nkt) {
            load_stage(cur ^ 1, kt + 1);
            asm volatile("cp.async.wait_group 1;\n");
        } else {
            asm volatile("cp.async.wait_group 0;\n");
        }
        __syncthreads();

        const float* pA = sA[cur];
        const float* pB = sB[cur];

#pragma unroll
        for (int kl = 0; kl < 16; kl += 8) {
            unsigned ahi[2][4], alo[2][4];
#pragma unroll
            for (int mt = 0; mt < 2; mt++) {
                int rb = wm + mt * 16 + lq;
                float a0 = pA[rb * 20 + kl + lr];
                float a1 = pA[(rb + 8) * 20 + kl + lr];
                float a2 = pA[rb * 20 + kl + lr + 4];
                float a3 = pA[(rb + 8) * 20 + kl + lr + 4];
                ahi[mt][0] = f2tf(a0); alo[mt][0] = f2tf(a0 - __uint_as_float(ahi[mt][0]));
                ahi[mt][1] = f2tf(a1); alo[mt][1] = f2tf(a1 - __uint_as_float(ahi[mt][1]));
                ahi[mt][2] = f2tf(a2); alo[mt][2] = f2tf(a2 - __uint_as_float(ahi[mt][2]));
                ahi[mt][3] = f2tf(a3); alo[mt][3] = f2tf(a3 - __uint_as_float(ahi[mt][3]));
            }
#pragma unroll
            for (int nt = 0; nt < 8; nt++) {
                int nr = wn + nt * 8 + lq;
                float b0 = pB[nr * 20 + kl + lr];
                float b1 = pB[nr * 20 + kl + lr + 4];
                unsigned bh0 = f2tf(b0), bh1 = f2tf(b1);
                unsigned bl0 = f2tf(b0 - __uint_as_float(bh0));
                unsigned bl1 = f2tf(b1 - __uint_as_float(bh1));
#pragma unroll
                for (int mt = 0; mt < 2; mt++) {
                    mma8(acc[mt][nt], alo[mt][0], alo[mt][1], alo[mt][2], alo[mt][3], bh0, bh1);
                    mma8(acc[mt][nt], ahi[mt][0], ahi[mt][1], ahi[mt][2], ahi[mt][3], bl0, bl1);
                    mma8(acc[mt][nt], ahi[mt][0], ahi[mt][1], ahi[mt][2], ahi[mt][3], bh0, bh1);
                }
            }
        }
        __syncthreads();
    }

#pragma unroll
    for (int mt = 0; mt < 2; mt++) {
#pragma unroll
        for (int nt = 0; nt < 8; nt++) {
            int row = m0 + wm + mt * 16 + lq;
            int col = n0 + wn + nt * 8 + lr * 2;
            float bc0 = bias ? bias[col]     : 0.0f;
            float bc1 = bias ? bias[col + 1] : 0.0f;
            float2 v0 = make_float2(acc[mt][nt][0] + bc0, acc[mt][nt][1] + bc1);
            float2 v1 = make_float2(acc[mt][nt][2] + bc0, acc[mt][nt][3] + bc1);
            *(float2*)&C[(long long)row * ldc + col]       = v0;
            *(float2*)&C[(long long)(row + 8) * ldc + col] = v1;
        }
    }
}

// =====================================================================
// Tensor-core tf32 (3xTF32) GEMM, C = A * B
//   A [M,K] rows stride lda;  B [K,N] rows stride ldb (N contiguous).
// =====================================================================
__global__ void __launch_bounds__(256)
tgemm_nn(int M, int N, int K,
         const float* __restrict__ A, long long lda, long long bsA,
         const float* __restrict__ B, long long ldb, long long bsB,
         float* __restrict__ C, long long ldc, long long bsC)
{
    __shared__ float sA[2][128 * 20];
    __shared__ float sB[2][16 * 132];

    const int tid = threadIdx.x;
    const int n0 = blockIdx.x * 128;
    const int m0 = blockIdx.y * 128;
    A += (long long)blockIdx.z * bsA;
    B += (long long)blockIdx.z * bsB;
    C += (long long)blockIdx.z * bsC;

    const int w    = tid >> 5;
    const int lane = tid & 31;
    const int lq   = lane >> 2;
    const int lr   = lane & 3;
    const int wm   = (w & 3) * 32;
    const int wn   = (w >> 2) * 64;

    float acc[2][8][4];
#pragma unroll
    for (int mt = 0; mt < 2; mt++)
#pragma unroll
        for (int nt = 0; nt < 8; nt++)
#pragma unroll
            for (int i = 0; i < 4; i++) acc[mt][nt][i] = 0.0f;

    const int nkt = K >> 4;

    auto load_stage = [&](int s, int kt) {
#pragma unroll
        for (int i = 0; i < 2; i++) {
            int idx = i * 256 + tid;
            int row = idx >> 2, c4 = idx & 3;
            cp_async16(&sA[s][row * 20 + c4 * 4],
                       A + (long long)(m0 + row) * lda + kt * 16 + c4 * 4);
            int kr = idx >> 5, nc = idx & 31;          // kr 0..15, nc float4 0..31
            cp_async16(&sB[s][kr * 132 + nc * 4],
                       B + (long long)(kt * 16 + kr) * ldb + n0 + nc * 4);
        }
        asm volatile("cp.async.commit_group;\n");
    };

    load_stage(0, 0);

    for (int kt = 0; kt < nkt; kt++) {
        int cur = kt & 1;
        if (kt + 1 < nkt) {
            load_stage(cur ^ 1, kt + 1);
            asm volatile("cp.async.wait_group 1;\n");
        } else {
            asm volatile("cp.async.wait_group 0;\n");
        }
        __syncthreads();

        const float* pA = sA[cur];
        const float* pB = sB[cur];

#pragma unroll
        for (int kl = 0; kl < 16; kl += 8) {
            unsigned ahi[2][4], alo[2][4];
#pragma unroll
            for (int mt = 0; mt < 2; mt++) {
                int rb = wm + mt * 16 + lq;
                float a0 = pA[rb * 20 + kl + lr];
                float a1 = pA[(rb + 8) * 20 + kl + lr];
                float a2 = pA[rb * 20 + kl + lr + 4];
                float a3 = pA[(rb + 8) * 20 + kl + lr + 4];
                ahi[mt][0] = f2tf(a0); alo[mt][0] = f2tf(a0 - __uint_as_float(ahi[mt][0]));
                ahi[mt][1] = f2tf(a1); alo[mt][1] = f2tf(a1 - __uint_as_float(ahi[mt][1]));
                ahi[mt][2] = f2tf(a2); alo[mt][2] = f2tf(a2 - __uint_as_float(ahi[mt][2]));
                ahi[mt][3] = f2tf(a3); alo[mt][3] = f2tf(a3 - __uint_as_float(ahi[mt][3]));
            }
#pragma unroll
            for (int nt = 0; nt < 8; nt++) {
                int nc = wn + nt * 8 + lq;
                float b0 = pB[(kl + lr) * 132 + nc];
                float b1 = pB[(kl + lr + 4) * 132 + nc];
                unsigned bh0 = f2tf(b0), bh1 = f2tf(b1);
                unsigned bl0 = f2tf(b0 - __uint_as_float(bh0));
                unsigned bl1 = f2tf(b1 - __uint_as_float(bh1));
#pragma unroll
                for (int mt = 0; mt < 2; mt++) {
                    mma8(acc[mt][nt], alo[mt][0], alo[mt][1], alo[mt][2], alo[mt][3], bh0, bh1);
                    mma8(acc[mt][nt], ahi[mt][0], ahi[mt][1], ahi[mt][2], ahi[mt][3], bl0, bl1);
                    mma8(acc[mt][nt], ahi[mt][0], ahi[mt][1], ahi[mt][2], ahi[mt][3], bh0, bh1);
                }
            }
        }
        __syncthreads();
    }

#pragma unroll
    for (int mt = 0; mt < 2; mt++) {
#pragma unroll
        for (int nt = 0; nt < 8; nt++) {
            int row = m0 + wm + mt * 16 + lq;
            int col = n0 + wn + nt * 8 + lr * 2;
            float2 v0 = make_float2(acc[mt][nt][0], acc[mt][nt][1]);
            float2 v1 = make_float2(acc[mt][nt][2], acc[mt][nt][3]);
            *(float2*)&C[(long long)row * ldc + col]       = v0;
            *(float2*)&C[(long long)(row + 8) * ldc + col] = v1;
        }
    }
}

// =====================================================================
// Persistent GRU recurrence (unchanged from R6 — runs at FFMA floor)
// =====================================================================
extern __shared__ float rsm[];   // [12*1024] W slice | 2 x [64*64] h chunk buffers

__global__ void __launch_bounds__(RTHREADS, 2)
gru_persistent(const float* __restrict__ gi,
               const float* __restrict__ W_hh,
               const float* __restrict__ b_hh,
               const float* __restrict__ h_init,
               const int* __restrict__ length,
               float* __restrict__ h2,          // [2][B*H]
               float* __restrict__ out_hs,      // [S][B][2H]
               float* __restrict__ out_hlast,   // [B][H]
               unsigned* __restrict__ bar)
{
    const int tid = threadIdx.x;
    const int bg  = tid >> 4;
    const int ks  = tid & 15;
    const int j0  = blockIdx.x * 4;
    const int b   = bg * 4 + (ks >> 2);
    const int j   = j0 + (ks & 3);

    float* Ws  = rsm;
    float* hb0 = rsm + 12 * 1024;
    float* hb1 = hb0 + 64 * 64;

    for (int v = tid; v < 12 * 256; v += RTHREADS) {
        int cc = v >> 8;
        int cq = v & 255;
        int row = (cc % 3) * 1024 + j0 + (cc / 3);
        ((float4*)Ws)[cc * 256 + cq] = ((const float4*)W_hh)[row * 256 + cq];
    }

    const float bh_r = b_hh[j];
    const float bh_z = b_hh[1024 + j];
    const float bh_n = b_hh[2048 + j];
    const int   len_b = length[b];

    {
        int v = blockIdx.x * RTHREADS + tid;
        h2[v] = h_init[v & (HDIM - 1)];
    }

    unsigned phase = 1;
    {
        __threadfence(); __syncthreads();
        if (tid == 0) {
            atomicAdd(bar, 1u);
            while (*((volatile unsigned*)bar) < phase * RBLOCKS) { __nanosleep(32); }
        }
        __syncthreads();
    }

    for (int s = 0; s < SEQ; s++) {
        const float* hcur = h2 + (s & 1) * (BATCH * HDIM);
        float*       hnxt = h2 + ((s + 1) & 1) * (BATCH * HDIM);
        const float4* hc4 = (const float4*)hcur;

        const float* gis = gi + (long long)s * (BATCH * 3 * HDIM) + b * 3 * HDIM;
        float gi_r  = __ldg(&gis[j]);
        float gi_z  = __ldg(&gis[1024 + j]);
        float gi_n  = __ldg(&gis[2048 + j]);
        float h_old = __ldcg(&hcur[b * 1024 + j]);

        float acc[4][12];
#pragma unroll
        for (int i = 0; i < 4; i++)
#pragma unroll
            for (int cc = 0; cc < 12; cc++) acc[i][cc] = 0.0f;

        {
            float4* dst = (float4*)hb0;
#pragma unroll
            for (int i = 0; i < 4; i++) {
                int idx = i * 256 + tid;
                int bb = idx >> 4, kq = idx & 15;
                cp_async16(&dst[bb * 16 + kq], &hc4[bb * 256 + kq]);
            }
            asm volatile("cp.async.commit_group;\n");
        }

        for (int c = 0; c < 16; c++) {
            const float* cur = (c & 1) ? hb1 : hb0;
            float*       nxt = (c & 1) ? hb0 : hb1;
            if (c + 1 < 16) {
                float4* dst = (float4*)nxt;
#pragma unroll
                for (int i = 0; i < 4; i++) {
                    int idx = i * 256 + tid;
                    int bb = idx >> 4, kq = idx & 15;
                    cp_async16(&dst[bb * 16 + kq], &hc4[bb * 256 + (c + 1) * 16 + kq]);
                }
                asm volatile("cp.async.commit_group;\n");
                asm volatile("cp.async.wait_group 1;\n");
            } else {
                asm volatile("cp.async.wait_group 0;\n");
            }
            __syncthreads();

            float4 ha[4];
#pragma unroll
            for (int i = 0; i < 4; i++)
                ha[i] = *(const float4*)&cur[(bg * 4 + i) * 64 + ks * 4];
#pragma unroll
            for (int cc = 0; cc < 12; cc++) {
                float4 wv = *(const float4*)&Ws[cc * 1024 + c * 64 + ks * 4];
#pragma unroll
                for (int i = 0; i < 4; i++) {
                    acc[i][cc] += ha[i].x * wv.x;
                    acc[i][cc] += ha[i].y * wv.y;
                    acc[i][cc] += ha[i].z * wv.z;
                    acc[i][cc] += ha[i].w * wv.w;
                }
            }
            __syncthreads();
        }

#pragma unroll
        for (int off = 8; off > 0; off >>= 1)
#pragma unroll
            for (int i = 0; i < 4; i++)
#pragma unroll
                for (int cc = 0; cc < 12; cc++)
                    acc[i][cc] += __shfl_xor_sync(0xffffffffu, acc[i][cc], off);

        {
            int bi = ks >> 2, jj = ks & 3;
            float ghr = acc[bi][jj * 3 + 0] + bh_r;
            float ghz = acc[bi][jj * 3 + 1] + bh_z;
            float ghn = acc[bi][jj * 3 + 2] + bh_n;
            float r = 1.0f / (1.0f + expf(-(gi_r + ghr)));
            float z = 1.0f / (1.0f + expf(-(gi_z + ghz)));
            float n = tanhf(gi_n + r * ghn);
            float keep = (s < len_b) ? 1.0f : 0.0f;
            float hnew = (n + z * (h_old - n)) * keep;

            hnxt[b * 1024 + j] = hnew;
            out_hs[(long long)s * (BATCH * 2 * HDIM) + b * (2 * HDIM) + j] = hnew;
            if (s == SEQ - 1) out_hlast[b * 1024 + j] = hnew;
        }

        phase++;
        __threadfence(); __syncthreads();
        if (tid == 0) {
            atomicAdd(bar, 1u);
            while (*((volatile unsigned*)bar) < phase * RBLOCKS) { __nanosleep(32); }
        }
        __syncthreads();
    }
}

// =====================================================================
// Softmax
// =====================================================================
__global__ void attn_softmax_kernel(const float* __restrict__ scores,   // [b][s][l]
                                    const int* __restrict__ post_length,
                                    float* __restrict__ attn_scratch,   // [b][s][l]
                                    float* __restrict__ out_attn)       // [s][l][b]
{
    int s = blockIdx.x;
    int b = blockIdx.y;
    int l = threadIdx.x;

    float sc = scores[((long long)b * SEQ + s) * PLEN + l];
    if (l >= post_length[b]) sc = -1000000000.0f;

    __shared__ float red[PLEN];
    red[l] = sc;
    __syncthreads();
#pragma unroll
    for (int o = PLEN / 2; o > 0; o >>= 1) {
        if (l < o) red[l] = fmaxf(red[l], red[l + o]);
        __syncthreads();
    }
    float mx = red[0];
    __syncthreads();

    float e = expf(sc - mx);
    red[l] = e;
    __syncthreads();
#pragma unroll
    for (int o = PLEN / 2; o > 0; o >>= 1) {
        if (l < o) red[l] += red[l + o];
        __syncthreads();
    }
    float a = e / red[0];

    attn_scratch[((long long)b * SEQ + s) * PLEN + l] = a;
    out_attn[(long long)s * (PLEN * BATCH) + l * BATCH + b] = a;
}

// =====================================================================
// launch
// =====================================================================
extern "C" void kernel_launch(void* const* d_in, const int* in_sizes, int n_in,
                              void* d_out, int out_size)
{
    (void)in_sizes; (void)n_in; (void)out_size;

    const float* incoming = (const float*)d_in[0];
    const float* post     = (const float*)d_in[1];
    const float* h_init   = (const float*)d_in[2];
    const float* W_ih     = (const float*)d_in[3];
    const float* W_hh     = (const float*)d_in[4];
    const float* b_ih     = (const float*)d_in[5];
    const float* b_hh     = (const float*)d_in[6];
    const float* Wq       = (const float*)d_in[7];
    const float* bq       = (const float*)d_in[8];
    const int*   length      = (const int*)d_in[9];
    const int*   post_length = (const int*)d_in[10];

    float* out       = (float*)d_out;
    float* out_hlast = out;                                   // [B, H]
    float* out_hs    = out + BATCH * HDIM;                    // [S, B, 2H]
    float* out_attn  = out_hs + (long long)SEQ * BATCH * 2 * HDIM;  // [S, PL, B]

    float *gi, *h2, *query, *scores, *attn;
    unsigned* bar;
    cudaGetSymbolAddress((void**)&gi,     g_gi);
    cudaGetSymbolAddress((void**)&h2,     g_h2);
    cudaGetSymbolAddress((void**)&query,  g_query);
    cudaGetSymbolAddress((void**)&scores, g_scores);
    cudaGetSymbolAddress((void**)&attn,   g_attn);
    cudaGetSymbolAddress((void**)&bar,    g_bar);

    cudaFuncSetAttribute(gru_persistent,
                         cudaFuncAttributeMaxDynamicSharedMemorySize, 81920);

    const int MALL = SEQ * BATCH;   // 16384

    // Phase A: gi = incoming @ W_ih^T + b_ih  [16384, 3072] k=1024
    tgemm_nt<<<dim3(3 * HDIM / 128, MALL / 128), 256>>>(
        MALL, 3 * HDIM, IDIM,
        incoming, IDIM, 0,
        W_ih, IDIM, 0,
        gi, 3 * HDIM, 0,
        b_ih);

    // Phase B: persistent fused GRU recurrence
    cudaMemsetAsync(bar, 0, sizeof(unsigned));
    gru_persistent<<<RBLOCKS, RTHREADS, 81920>>>(
        gi, W_hh, b_hh, h_init, length, h2, out_hs, out_hlast, bar);

    // Phase C: query = h_all @ Wq^T + bq (h read from hs region, stride 2H)
    tgemm_nt<<<dim3(PDIM / 128, MALL / 128), 256>>>(
        MALL, PDIM, HDIM,
        out_hs, 2 * HDIM, 0,
        Wq, HDIM, 0,
        query, PDIM, 0,
        bq);

    // Phase D1: scores_b = Q_b @ post_b^T (batched over b)
    tgemm_nt<<<dim3(PLEN / 128, SEQ / 128, BATCH), 256>>>(
        SEQ, PLEN, PDIM,
        query, (long long)BATCH * PDIM, PDIM,
        post, (long long)BATCH * PDIM, PDIM,
        scores, PLEN, (long long)SEQ * PLEN,
        (const float*)nullptr);

    // Phase D2: masked softmax over l
    attn_softmax_kernel<<<dim3(SEQ, BATCH), PLEN>>>(scores, post_length, attn, out_attn);

    // Phase D3: context_b = attn_b @ post_b
    tgemm_nn<<<dim3(PDIM / 128, SEQ / 128, BATCH), 256>>>(
        SEQ, PDIM, PLEN,
        attn, PLEN, (long long)SEQ * PLEN,
        post, (long long)BATCH * PDIM, PDIM,
        out_hs + HDIM, (long long)BATCH * 2 * HDIM, 2 * HDIM);
}